// round 15
// baseline (speedup 1.0000x reference)
#include <cuda_runtime.h>
#include <cuda_bf16.h>
#include <cstdint>

// Problem constants
#define N        8192
#define IN_DIM   512
#define NCLASS   16
#define PC       512      // per class
#define KK       256      // kept per class
#define NSEL     4096     // NCLASS * KK

// Output layout (single f32 buffer): M_out | X_out | mask_out
#define M_OUT_OFF    0
#define X_OUT_OFF    (NSEL * (size_t)NSEL)               // 16777216
#define MASK_OUT_OFF (X_OUT_OFF + NSEL * (size_t)IN_DIM) // 18874368

// Single persistent grid: 3 blocks/SM * 148 SMs (one wave, guaranteed)
#define PGRID  444
#define NWARPS (PGRID * 16)     // 7104 global warps

// Scratch (device globals — no allocation allowed)
#define CNT_STRIDE 64
__device__ int                g_idx[NSEL];
__device__ float              g_vals[NSEL];
__device__ unsigned           g_cnt[NCLASS * CNT_STRIDE];  // monotone; pos = old & 511
__device__ unsigned           g_bar1;   // +PGRID per run
__device__ unsigned           g_bar2;   // +NCLASS per run
__device__ unsigned long long g_keys[N];

// ---------------------------------------------------------------------------
// Bit-replica of XLA:CPU / Eigen Cephes expf (confirmed bit-exact: R5 w=0).
// ---------------------------------------------------------------------------
__device__ __forceinline__ float cephes_expf(float r) {
    float in = fminf(fmaxf(r, -88.3762626647949f), 88.3762626647950f);
    float fx = floorf(__fmaf_rn(in, 1.44269504088896341f, 0.5f));
    float tmp = __fmul_rn(0.693359375f, fx);
    float zz  = __fmul_rn(-2.12194440e-4f, fx);
    float x   = __fsub_rn(__fsub_rn(in, tmp), zz);
    float z2  = __fmul_rn(x, x);
    float y   = __fmaf_rn(x, 1.9875691500E-4f, 1.3981999507E-3f);
    y = __fmaf_rn(y, x, 8.3334519073E-3f);
    y = __fmaf_rn(y, x, 4.1665795894E-2f);
    y = __fmaf_rn(y, x, 1.6666665459E-1f);
    y = __fmaf_rn(y, x, 5.0000001201E-1f);
    y = __fmaf_rn(y, z2, x);
    y = __fadd_rn(1.0f, y);
    int n = (int)fx;
    float pow2n = __int_as_float((unsigned)(n + 127) << 23);
    return __fmul_rn(y, pow2n);
}

__device__ __forceinline__ unsigned long long cex_shfl(unsigned long long v,
                                                       int s, bool asc, int e) {
    unsigned long long o = __shfl_xor_sync(0xffffffffu, v, s);
    bool lower   = (e & s) == 0;
    bool keepMin = (lower == asc);
    return keepMin ? (o < v ? o : v) : (o > v ? o : v);
}

// cp.async helpers
__device__ __forceinline__ void cp_async16(uint32_t saddr, const void* gptr) {
    asm volatile("cp.async.cg.shared.global [%0], [%1], 16;\n"
                 :: "r"(saddr), "l"(gptr));
}
__device__ __forceinline__ void cp_commit() {
    asm volatile("cp.async.commit_group;\n");
}
template <int NN>
__device__ __forceinline__ void cp_wait() {
    asm volatile("cp.async.wait_group %0;\n" :: "n"(NN));
}
__device__ __forceinline__ void stcs4(float* p, float4 v) {
    asm volatile("st.global.cs.v4.f32 [%0], {%1,%2,%3,%4};\n"
                 :: "l"(p), "f"(v.x), "f"(v.y), "f"(v.z), "f"(v.w));
}

extern __shared__ float s_buf[];   // 64KB: moutx double buffer; sort keys overlay

__device__ __forceinline__ void issue_row(const float* __restrict__ M,
                                          int ri, int bufsel) {
    uint32_t sbase = (uint32_t)__cvta_generic_to_shared(&s_buf[bufsel * N]);
    const char* g = (const char*)(M + (size_t)ri * N);
    int t = threadIdx.x;
#pragma unroll
    for (int i = 0; i < 4; ++i) {
        int off16 = (t + i * 512) * 16;
        cp_async16(sbase + off16, g + off16);
    }
    cp_commit();
}

// ---------------------------------------------------------------------------
// Score one row (warp-collective); returns packed key on lane 0.
// Bit-exact selection arithmetic (Cephes sigmoid, exact-RN glue).
// ---------------------------------------------------------------------------
__device__ __forceinline__ void score_one(const float* __restrict__ X,
                                          float4 q0, float4 q1, float4 q2, float4 q3,
                                          float bb, int row, int is64,
                                          const int* __restrict__ mask_i32,
                                          int lane) {
    const float4* xr = (const float4*)(X + (size_t)row * IN_DIM);
    float4 a0 = xr[lane], a1 = xr[lane + 32], a2 = xr[lane + 64], a3 = xr[lane + 96];

    float s0 = __fmul_rn(a0.x, q0.x), s1 = __fmul_rn(a0.y, q0.y);
    float s2 = __fmul_rn(a0.z, q0.z), s3 = __fmul_rn(a0.w, q0.w);
    s0 = __fmaf_rn(a1.x, q1.x, s0); s1 = __fmaf_rn(a1.y, q1.y, s1);
    s2 = __fmaf_rn(a1.z, q1.z, s2); s3 = __fmaf_rn(a1.w, q1.w, s3);
    s0 = __fmaf_rn(a2.x, q2.x, s0); s1 = __fmaf_rn(a2.y, q2.y, s1);
    s2 = __fmaf_rn(a2.z, q2.z, s2); s3 = __fmaf_rn(a2.w, q2.w, s3);
    s0 = __fmaf_rn(a3.x, q3.x, s0); s1 = __fmaf_rn(a3.y, q3.y, s1);
    s2 = __fmaf_rn(a3.z, q3.z, s2); s3 = __fmaf_rn(a3.w, q3.w, s3);
    float s = __fadd_rn(__fadd_rn(s0, s1), __fadd_rn(s2, s3));
#pragma unroll
    for (int o = 16; o > 0; o >>= 1)
        s += __shfl_xor_sync(0xffffffffu, s, o);

    if (lane == 0) {
        float x  = __fdiv_rn(__fadd_rn(s, bb), 100.0f);
        float sc = __fdiv_rn(1.0f, __fadd_rn(1.0f, cephes_expf(-x)));
        int cls = is64 ? mask_i32[2 * row] : mask_i32[row];
        unsigned pos = atomicAdd(&g_cnt[cls * CNT_STRIDE], 1u) & (PC - 1);
        g_keys[cls * PC + pos] =
            ((unsigned long long)__float_as_uint(sc) << 32) | (unsigned)row;
    }
}

// ---------------------------------------------------------------------------
// THE kernel: 444 blocks x 512 threads, 64KB dyn smem, single co-resident
// wave (enforced by __launch_bounds__(512,3)).
// Phase 1: score (all blocks; 1-2 rows/warp)      -> barrier1 (all 444)
// Phase 2: blocks 0..15 sort their class          -> barrier2 (16 arrivals)
// Phase 3: all blocks run the pipelined M/X gather.
// Monotone barrier counters survive graph replays (+444 / +16 per run).
// ---------------------------------------------------------------------------
__global__ __launch_bounds__(512, 3) void mega_kernel(
        const float* __restrict__ M,
        const float* __restrict__ X,
        const int* __restrict__ mask_i32,
        const float* __restrict__ W,
        const float* __restrict__ b,
        float* __restrict__ out) {
    const int tid  = threadIdx.x;
    const int wid  = tid >> 5;
    const int lane = tid & 31;
    __shared__ unsigned s_tgt1, s_base2;

    // read barrier2 base BEFORE arriving at barrier1 (sorters can't bump
    // g_bar2 until all 444 blocks pass their barrier1 arrival) — race-free.
    if (tid == 0) s_base2 = *(volatile unsigned*)&g_bar2;

    // is64: odd int32 words of first 32 entries all zero <=> int64 layout
    int nz = (mask_i32[2 * lane + 1] != 0);
    const int is64 = (__ballot_sync(0xffffffffu, nz) == 0u) ? 1 : 0;

    // ---- Phase 1: score. global warp id -> rows wg, wg + NWARPS ----
    const float4* w4 = (const float4*)W;
    float4 q0 = __ldg(&w4[lane +  0]), q1 = __ldg(&w4[lane + 32]),
           q2 = __ldg(&w4[lane + 64]), q3 = __ldg(&w4[lane + 96]);
    const float bb = b[0];
    const int wg = blockIdx.x * 16 + wid;

    score_one(X, q0, q1, q2, q3, bb, wg, is64, mask_i32, lane);          // rows 0..7103
    if (wg + NWARPS < N)
        score_one(X, q0, q1, q2, q3, bb, wg + NWARPS, is64, mask_i32, lane);
    __syncthreads();

    // ---- barrier1 arrival ----
    if (tid == 0) {
        __threadfence();
        unsigned old = atomicAdd(&g_bar1, 1u);
        s_tgt1 = old - (old % PGRID) + PGRID;
    }
    __syncthreads();

    // ---- Phase 2: per-class sort on blocks 0..15 ----
    if (blockIdx.x < NCLASS) {
        if (tid == 0) {
            unsigned tgt = s_tgt1;
            volatile unsigned* dp = &g_bar1;
            while (*dp < tgt) { }
            __threadfence();
        }
        __syncthreads();

        unsigned long long* keys = (unsigned long long*)s_buf;
        const int j = blockIdx.x;
        unsigned long long v = g_keys[j * PC + tid];

#pragma unroll
        for (unsigned k = 2; k <= 32; k <<= 1) {
            bool asc = ((tid & k) == 0);
            for (int s = k >> 1; s >= 1; s >>= 1)
                v = cex_shfl(v, s, asc, tid);
        }
        keys[tid] = v;

#pragma unroll
        for (unsigned k = 64; k <= PC; k <<= 1) {
            for (unsigned s = k >> 1; s >= 32; s >>= 1) {
                __syncthreads();
                unsigned partner = tid ^ s;
                if (partner > (unsigned)tid) {
                    unsigned long long a  = keys[tid];
                    unsigned long long bo = keys[partner];
                    bool ascending = ((tid & k) == 0);
                    if ((a > bo) == ascending) {
                        keys[tid]     = bo;
                        keys[partner] = a;
                    }
                }
            }
            __syncthreads();
            v = keys[tid];
            bool asc = ((tid & k) == 0);
#pragma unroll
            for (int s = 16; s >= 1; s >>= 1)
                v = cex_shfl(v, s, asc, tid);
            keys[tid] = v;
        }

        if (tid < KK) {
            int o = j * KK + tid;
            g_idx[o]  = (int)(unsigned)(v & 0xffffffffu);
            g_vals[o] = __uint_as_float((unsigned)(v >> 32));
            out[MASK_OUT_OFF + o] = (float)j;
        }
        __syncthreads();
        if (tid == 0) {
            __threadfence();
            atomicAdd(&g_bar2, 1u);
        }
    }

    // ---- barrier2 wait (all blocks) ----
    if (tid == 0) {
        unsigned tgt = s_base2 + NCLASS;
        volatile unsigned* dp = &g_bar2;
        while (*dp < tgt) { }
        __threadfence();
    }
    __syncthreads();

    // ---- Phase 3: persistent pipelined M/X gather ----
    const int r0 = blockIdx.x;
    if (r0 < NSEL)          issue_row(M, g_idx[r0], 0);
    if (r0 + PGRID < NSEL)  issue_row(M, g_idx[r0 + PGRID], 1);

    int buf = 0;
    for (int r = r0; r < NSEL; r += PGRID, buf ^= 1) {
        int nn = r + 2 * PGRID;
        if (nn < NSEL) { cp_wait<1>(); } else { cp_wait<0>(); }
        __syncthreads();

        if (tid < 128) {
            float v = g_vals[r];
            float4 x = ((const float4*)(X + (size_t)g_idx[r] * IN_DIM))[tid];
            stcs4((float*)(((float4*)(out + X_OUT_OFF + (size_t)r * IN_DIM)) + tid),
                  make_float4(x.x * v, x.y * v, x.z * v, x.w * v));
        }

        const float* row = &s_buf[buf * N];
        float4* dst4 = (float4*)(out + M_OUT_OFF + (size_t)r * NSEL);
        const int4* gi4 = (const int4*)g_idx;
#pragma unroll
        for (int i = 0; i < 2; ++i) {
            int c = tid + i * 512;
            int4 ii = gi4[c];
            float4 o;
            o.x = row[ii.x];
            o.y = row[ii.y];
            o.z = row[ii.z];
            o.w = row[ii.w];
            stcs4((float*)(dst4 + c), o);
        }
        __syncthreads();              // buffer fully consumed before refill

        if (nn < NSEL) issue_row(M, g_idx[nn], buf);
    }
}

// ---------------------------------------------------------------------------
extern "C" void kernel_launch(void* const* d_in, const int* in_sizes, int n_in,
                              void* d_out, int out_size) {
    const float* M    = (const float*)d_in[0];
    const float* X    = (const float*)d_in[1];
    const int*   mask = (const int*)  d_in[2];
    const float* W    = (const float*)d_in[3];
    const float* b    = (const float*)d_in[4];
    float* out = (float*)d_out;

    static const size_t SMEM = 2 * N * sizeof(float);   // 64 KB
    cudaFuncSetAttribute(mega_kernel,
                         cudaFuncAttributeMaxDynamicSharedMemorySize,
                         (int)SMEM);

    mega_kernel<<<PGRID, 512, SMEM>>>(M, X, mask, W, b, out);
}

// round 16
// speedup vs baseline: 1.0182x; 1.0182x over previous
#include <cuda_runtime.h>
#include <cuda_bf16.h>
#include <cstdint>

// Problem constants
#define N        8192
#define IN_DIM   512
#define NCLASS   16
#define PC       512      // per class
#define KK       256      // kept per class
#define NSEL     4096     // NCLASS * KK

// Output layout (single f32 buffer): M_out | X_out | mask_out
#define M_OUT_OFF    0
#define X_OUT_OFF    (NSEL * (size_t)NSEL)               // 16777216
#define MASK_OUT_OFF (X_OUT_OFF + NSEL * (size_t)IN_DIM) // 18874368

// Persistent moutx grid: 3 blocks/SM * 148 SMs
#define PGRID 444
// Fused score+sort grid: 128 blocks x 16 warps x 4 rows = 8192 rows
#define SGRID 128

// Scratch (device globals — no allocation allowed)
#define CNT_STRIDE 64
__device__ int                g_idx[NSEL];
__device__ float              g_vals[NSEL];
__device__ unsigned           g_cnt[NCLASS * CNT_STRIDE];  // monotone; pos = old & 511
__device__ unsigned           g_done;                      // monotone; +SGRID per run
__device__ unsigned long long g_keys[N];

// ---------------------------------------------------------------------------
// Bit-replica of XLA:CPU / Eigen Cephes expf (confirmed bit-exact: R5 w=0).
// ---------------------------------------------------------------------------
__device__ __forceinline__ float cephes_expf(float r) {
    float in = fminf(fmaxf(r, -88.3762626647949f), 88.3762626647950f);
    float fx = floorf(__fmaf_rn(in, 1.44269504088896341f, 0.5f));
    float tmp = __fmul_rn(0.693359375f, fx);
    float zz  = __fmul_rn(-2.12194440e-4f, fx);
    float x   = __fsub_rn(__fsub_rn(in, tmp), zz);
    float z2  = __fmul_rn(x, x);
    float y   = __fmaf_rn(x, 1.9875691500E-4f, 1.3981999507E-3f);
    y = __fmaf_rn(y, x, 8.3334519073E-3f);
    y = __fmaf_rn(y, x, 4.1665795894E-2f);
    y = __fmaf_rn(y, x, 1.6666665459E-1f);
    y = __fmaf_rn(y, x, 5.0000001201E-1f);
    y = __fmaf_rn(y, z2, x);
    y = __fadd_rn(1.0f, y);
    int n = (int)fx;
    float pow2n = __int_as_float((unsigned)(n + 127) << 23);
    return __fmul_rn(y, pow2n);
}

__device__ __forceinline__ unsigned long long cex_shfl(unsigned long long v,
                                                       int s, bool asc, int e) {
    unsigned long long o = __shfl_xor_sync(0xffffffffu, v, s);
    bool lower   = (e & s) == 0;
    bool keepMin = (lower == asc);
    return keepMin ? (o < v ? o : v) : (o > v ? o : v);
}

// Dot of a preloaded row (a0..a3) with W regs — exact-RN pattern (unchanged).
__device__ __forceinline__ float dot_row(float4 a0, float4 a1, float4 a2, float4 a3,
                                         float4 q0, float4 q1, float4 q2, float4 q3) {
    float s0 = __fmul_rn(a0.x, q0.x), s1 = __fmul_rn(a0.y, q0.y);
    float s2 = __fmul_rn(a0.z, q0.z), s3 = __fmul_rn(a0.w, q0.w);
    s0 = __fmaf_rn(a1.x, q1.x, s0); s1 = __fmaf_rn(a1.y, q1.y, s1);
    s2 = __fmaf_rn(a1.z, q1.z, s2); s3 = __fmaf_rn(a1.w, q1.w, s3);
    s0 = __fmaf_rn(a2.x, q2.x, s0); s1 = __fmaf_rn(a2.y, q2.y, s1);
    s2 = __fmaf_rn(a2.z, q2.z, s2); s3 = __fmaf_rn(a2.w, q2.w, s3);
    s0 = __fmaf_rn(a3.x, q3.x, s0); s1 = __fmaf_rn(a3.y, q3.y, s1);
    s2 = __fmaf_rn(a3.z, q3.z, s2); s3 = __fmaf_rn(a3.w, q3.w, s3);
    return __fadd_rn(__fadd_rn(s0, s1), __fadd_rn(s2, s3));
}

// ---------------------------------------------------------------------------
// Kernel 1 (fused score + scatter + spin barrier + per-class sort).
// Grid 128 x 512. Each warp scores 4 rows with ALL 16 X-loads issued
// before consumption (8KB in flight per warp -> DRAM-limited, not
// latency-limited). Scatter via 256B-strided counters. Blocks 0..15 then
// spin on g_done (monotone, +SGRID per run) and sort their class.
// ---------------------------------------------------------------------------
__global__ __launch_bounds__(512) void score_sort_kernel(
        const float* __restrict__ X,
        const float* __restrict__ W,
        const float* __restrict__ b,
        const int* __restrict__ mask_i32,
        float* __restrict__ out) {
    __shared__ unsigned long long keys[PC];
    __shared__ unsigned s_target;

    const int tid  = threadIdx.x;          // 0..511
    const int wid  = tid >> 5;
    const int lane = tid & 31;

    // warp-local is64 detection (odd int32 words of first 32 entries)
    int nz = (mask_i32[2 * lane + 1] != 0);
    const int is64 = (__ballot_sync(0xffffffffu, nz) == 0u) ? 1 : 0;

    // --- score 4 rows per warp; issue all 16 X loads up front ---
    const int r0 = (blockIdx.x * 16 + wid) * 4;
    const float4* x0 = (const float4*)(X + (size_t)(r0 + 0) * IN_DIM);
    const float4* x1 = (const float4*)(X + (size_t)(r0 + 1) * IN_DIM);
    const float4* x2 = (const float4*)(X + (size_t)(r0 + 2) * IN_DIM);
    const float4* x3 = (const float4*)(X + (size_t)(r0 + 3) * IN_DIM);
    const float4* w4 = (const float4*)W;

    float4 a0 = x0[lane], a1 = x0[lane + 32], a2 = x0[lane + 64], a3 = x0[lane + 96];
    float4 b0 = x1[lane], b1 = x1[lane + 32], b2 = x1[lane + 64], b3 = x1[lane + 96];
    float4 c0 = x2[lane], c1 = x2[lane + 32], c2 = x2[lane + 64], c3 = x2[lane + 96];
    float4 d0 = x3[lane], d1 = x3[lane + 32], d2 = x3[lane + 64], d3 = x3[lane + 96];
    float4 q0 = __ldg(&w4[lane +  0]), q1 = __ldg(&w4[lane + 32]),
           q2 = __ldg(&w4[lane + 64]), q3 = __ldg(&w4[lane + 96]);

    float sA = dot_row(a0, a1, a2, a3, q0, q1, q2, q3);
    float sB = dot_row(b0, b1, b2, b3, q0, q1, q2, q3);
    float sC = dot_row(c0, c1, c2, c3, q0, q1, q2, q3);
    float sD = dot_row(d0, d1, d2, d3, q0, q1, q2, q3);

#pragma unroll
    for (int o = 16; o > 0; o >>= 1) {
        sA += __shfl_xor_sync(0xffffffffu, sA, o);
        sB += __shfl_xor_sync(0xffffffffu, sB, o);
        sC += __shfl_xor_sync(0xffffffffu, sC, o);
        sD += __shfl_xor_sync(0xffffffffu, sD, o);
    }

    if (lane == 0) {
        const float bbv = b[0];
        float sc[4];
        sc[0] = __fdiv_rn(1.0f, __fadd_rn(1.0f,
                    cephes_expf(-__fdiv_rn(__fadd_rn(sA, bbv), 100.0f))));
        sc[1] = __fdiv_rn(1.0f, __fadd_rn(1.0f,
                    cephes_expf(-__fdiv_rn(__fadd_rn(sB, bbv), 100.0f))));
        sc[2] = __fdiv_rn(1.0f, __fadd_rn(1.0f,
                    cephes_expf(-__fdiv_rn(__fadd_rn(sC, bbv), 100.0f))));
        sc[3] = __fdiv_rn(1.0f, __fadd_rn(1.0f,
                    cephes_expf(-__fdiv_rn(__fadd_rn(sD, bbv), 100.0f))));
#pragma unroll
        for (int r = 0; r < 4; ++r) {
            int row = r0 + r;
            int cls = is64 ? mask_i32[2 * row] : mask_i32[row];
            unsigned pos = atomicAdd(&g_cnt[cls * CNT_STRIDE], 1u) & (PC - 1);
            g_keys[cls * PC + pos] =
                ((unsigned long long)__float_as_uint(sc[r]) << 32) | (unsigned)row;
        }
    }
    __syncthreads();

    // --- global barrier arrival ---
    if (tid == 0) {
        __threadfence();
        unsigned old = atomicAdd(&g_done, 1u);
        s_target = old - (old % SGRID) + SGRID;
    }

    if (blockIdx.x >= NCLASS) return;      // non-sorters exit

    __syncthreads();
    if (tid == 0) {
        unsigned tgt = s_target;
        volatile unsigned* dp = &g_done;
        while (*dp < tgt) { }
        __threadfence();
    }
    __syncthreads();

    // --- per-class hybrid bitonic sort (class j = blockIdx.x) ---
    const int j = blockIdx.x;
    unsigned long long v = g_keys[j * PC + tid];

#pragma unroll
    for (unsigned k = 2; k <= 32; k <<= 1) {
        bool asc = ((tid & k) == 0);
        for (int s = k >> 1; s >= 1; s >>= 1)
            v = cex_shfl(v, s, asc, tid);
    }
    keys[tid] = v;

#pragma unroll
    for (unsigned k = 64; k <= PC; k <<= 1) {
        for (unsigned s = k >> 1; s >= 32; s >>= 1) {
            __syncthreads();
            unsigned partner = tid ^ s;
            if (partner > (unsigned)tid) {
                unsigned long long a  = keys[tid];
                unsigned long long bo = keys[partner];
                bool ascending = ((tid & k) == 0);
                if ((a > bo) == ascending) {
                    keys[tid]     = bo;
                    keys[partner] = a;
                }
            }
        }
        __syncthreads();
        v = keys[tid];
        bool asc = ((tid & k) == 0);
#pragma unroll
        for (int s = 16; s >= 1; s >>= 1)
            v = cex_shfl(v, s, asc, tid);
        keys[tid] = v;
    }

    if (tid < KK) {
        int o = j * KK + tid;
        g_idx[o]  = (int)(unsigned)(v & 0xffffffffu);
        g_vals[o] = __uint_as_float((unsigned)(v >> 32));
        out[MASK_OUT_OFF + o] = (float)j;   // mask[idx] == class id by construction
    }
}

// ---------------------------------------------------------------------------
// cp.async helpers
// ---------------------------------------------------------------------------
__device__ __forceinline__ void cp_async16(uint32_t saddr, const void* gptr) {
    asm volatile("cp.async.cg.shared.global [%0], [%1], 16;\n"
                 :: "r"(saddr), "l"(gptr));
}
__device__ __forceinline__ void cp_commit() {
    asm volatile("cp.async.commit_group;\n");
}
template <int NN>
__device__ __forceinline__ void cp_wait() {
    asm volatile("cp.async.wait_group %0;\n" :: "n"(NN));
}
__device__ __forceinline__ void stcs4(float* p, float4 v) {
    asm volatile("st.global.cs.v4.f32 [%0], {%1,%2,%3,%4};\n"
                 :: "l"(p), "f"(v.x), "f"(v.y), "f"(v.z), "f"(v.w));
}

// ---------------------------------------------------------------------------
// Kernel 2 (persistent, pipelined; confirmed at the mixed R/W HBM floor):
// grid = 444 blocks (3/SM, single wave); block i handles rows i, i+444, ...
// with a double-buffered cp.async pipeline; streaming stores.
//   X_out[r,:] = X[idx[r],:] * vals[r]
//   M_out[r,c] = M[idx[r], idx[c]]
// ---------------------------------------------------------------------------
extern __shared__ float s_buf[];   // [2][N]

__device__ __forceinline__ void issue_row(const float* __restrict__ M,
                                          int ri, int bufsel) {
    uint32_t sbase = (uint32_t)__cvta_generic_to_shared(&s_buf[bufsel * N]);
    const char* g = (const char*)(M + (size_t)ri * N);
    int t = threadIdx.x;
#pragma unroll
    for (int i = 0; i < 4; ++i) {
        int off16 = (t + i * 512) * 16;
        cp_async16(sbase + off16, g + off16);
    }
    cp_commit();
}

__global__ __launch_bounds__(512) void moutx_kernel(const float* __restrict__ M,
                                                    const float* __restrict__ X,
                                                    float* __restrict__ out) {
    const int t = threadIdx.x;
    const int r0 = blockIdx.x;

    if (r0 < NSEL)          issue_row(M, g_idx[r0], 0);
    if (r0 + PGRID < NSEL)  issue_row(M, g_idx[r0 + PGRID], 1);

    int buf = 0;
    for (int r = r0; r < NSEL; r += PGRID, buf ^= 1) {
        int nn = r + 2 * PGRID;
        if (nn < NSEL) { cp_wait<1>(); } else { cp_wait<0>(); }
        __syncthreads();

        if (t < 128) {
            float v = g_vals[r];
            float4 x = ((const float4*)(X + (size_t)g_idx[r] * IN_DIM))[t];
            stcs4((float*)(((float4*)(out + X_OUT_OFF + (size_t)r * IN_DIM)) + t),
                  make_float4(x.x * v, x.y * v, x.z * v, x.w * v));
        }

        const float* row = &s_buf[buf * N];
        float4* dst4 = (float4*)(out + M_OUT_OFF + (size_t)r * NSEL);
        const int4* gi4 = (const int4*)g_idx;
#pragma unroll
        for (int i = 0; i < 2; ++i) {
            int c = t + i * 512;
            int4 ii = gi4[c];
            float4 o;
            o.x = row[ii.x];
            o.y = row[ii.y];
            o.z = row[ii.z];
            o.w = row[ii.w];
            stcs4((float*)(dst4 + c), o);
        }
        __syncthreads();              // buffer fully consumed before refill

        if (nn < NSEL) issue_row(M, g_idx[nn], buf);
    }
}

// ---------------------------------------------------------------------------
extern "C" void kernel_launch(void* const* d_in, const int* in_sizes, int n_in,
                              void* d_out, int out_size) {
    const float* M    = (const float*)d_in[0];
    const float* X    = (const float*)d_in[1];
    const int*   mask = (const int*)  d_in[2];
    const float* W    = (const float*)d_in[3];
    const float* b    = (const float*)d_in[4];
    float* out = (float*)d_out;

    static const size_t MOUT_SMEM = 2 * N * sizeof(float);   // 64 KB
    cudaFuncSetAttribute(moutx_kernel,
                         cudaFuncAttributeMaxDynamicSharedMemorySize,
                         (int)MOUT_SMEM);

    score_sort_kernel<<<SGRID, 512>>>(X, W, b, mask, out);
    moutx_kernel<<<PGRID, 512, MOUT_SMEM>>>(M, X, out);
}